// round 7
// baseline (speedup 1.0000x reference)
#include <cuda_runtime.h>
#include <cstdint>

#define N_NODES 100000
#define D_IN    512
#define D_H     128
#define NX      (N_NODES * D_IN)
#define NH      (N_NODES * D_H)
#define N_EDGES 1600000

__device__ __align__(16) float g_x[NX];
__device__ __align__(16) float g_h[NH];
__device__ __align__(16) float g_vals[N_EDGES];
__device__ double g_sum[D_H];
__device__ double g_sumsq[D_H];
__device__ float  g_scale[D_H];
__device__ float  g_shift[D_H];

__host__ __device__ __forceinline__ void tf2x32(unsigned k0, unsigned k1,
                                                unsigned &x0, unsigned &x1) {
  unsigned k2 = k0 ^ k1 ^ 0x1BD11BDAu;
  x0 += k0; x1 += k1;
#define TFR(r) { x0 += x1; x1 = (x1 << (r)) | (x1 >> (32 - (r))); x1 ^= x0; }
  TFR(13) TFR(15) TFR(26) TFR(6)   x0 += k1; x1 += k2 + 1u;
  TFR(17) TFR(29) TFR(16) TFR(24)  x0 += k2; x1 += k0 + 2u;
  TFR(13) TFR(15) TFR(26) TFR(6)   x0 += k0; x1 += k1 + 3u;
  TFR(17) TFR(29) TFR(16) TFR(24)  x0 += k1; x1 += k2 + 4u;
  TFR(13) TFR(15) TFR(26) TFR(6)   x0 += k2; x1 += k0 + 5u;
#undef TFR
}

__device__ __forceinline__ unsigned rbits32(unsigned k0, unsigned k1, unsigned i) {
  unsigned x0 = 0u, x1 = i;
  tf2x32(k0, k1, x0, x1);
  return x0 ^ x1;
}

__device__ __forceinline__ float u01(unsigned b) {
  return __uint_as_float((b >> 9) | 0x3F800000u) - 1.0f;
}

__device__ __forceinline__ float erfinv_xla(float x) {
  float w = -log1pf(-x * x);
  float p;
  if (w < 5.0f) {
    w -= 2.5f;
    p = 2.81022636e-08f;
    p = fmaf(p, w, 3.43273939e-07f);
    p = fmaf(p, w, -3.5233877e-06f);
    p = fmaf(p, w, -4.39150654e-06f);
    p = fmaf(p, w, 0.00021858087f);
    p = fmaf(p, w, -0.00125372503f);
    p = fmaf(p, w, -0.00417768164f);
    p = fmaf(p, w, 0.246640727f);
    p = fmaf(p, w, 1.50140941f);
  } else {
    w = sqrtf(w) - 3.0f;
    p = -0.000200214257f;
    p = fmaf(p, w, 0.000100950558f);
    p = fmaf(p, w, 0.00134934322f);
    p = fmaf(p, w, -0.00367342844f);
    p = fmaf(p, w, 0.00573950773f);
    p = fmaf(p, w, -0.0076224613f);
    p = fmaf(p, w, 0.00943887047f);
    p = fmaf(p, w, 1.00167406f);
    p = fmaf(p, w, 2.83297682f);
  }
  return p * x;
}

__device__ __forceinline__ float normal32(unsigned b) {
  const float LO = -0.99999994f;
  float f = u01(b);
  float u = fmaxf(LO, f * 2.0f + LO);
  return 1.4142135381698608f * erfinv_xla(u);
}

__device__ __forceinline__ unsigned f2tf32(float f) {
  unsigned r;
  asm("cvt.rna.tf32.f32 %0, %1;" : "=r"(r) : "f"(f));
  return r;
}

__global__ void zero_stats_kernel() {
  g_sum[threadIdx.x] = 0.0;
  g_sumsq[threadIdx.x] = 0.0;
}

__global__ void rng_x_kernel(const float* __restrict__ data,
                             unsigned kn0, unsigned kn1,
                             unsigned ka0, unsigned ka1,
                             unsigned kb0, unsigned kb1) {
  int t = blockIdx.x * blockDim.x + threadIdx.x;
  if (t >= NX / 4) return;
  int base = t * 4;
  float4 d = *((const float4*)data + t);
  float dv[4] = {d.x, d.y, d.z, d.w};
  float o[4];
#pragma unroll
  for (int e = 0; e < 4; e++) {
    unsigned i = (unsigned)(base + e);
    unsigned b1 = rbits32(ka0, ka1, i);
    unsigned b2 = rbits32(kb0, kb1, i);
    if (((b1 | b2) & 0x80000000u) == 0u) {
      float n = normal32(rbits32(kn0, kn1, i));
      o[e] = (dv[e] + 0.01f * n) * 4.0f;
    } else {
      o[e] = 0.0f;
    }
  }
  *((float4*)g_x + t) = make_float4(o[0], o[1], o[2], o[3]);
}

__global__ void edge_kernel(const float* __restrict__ adj_vals,
                            unsigned ke0, unsigned ke1) {
  int j = blockIdx.x * blockDim.x + threadIdx.x;
  if (j >= N_EDGES) return;
  unsigned b = rbits32(ke0, ke1, (unsigned)j);
  g_vals[j] = (u01(b) < 0.6f) ? (adj_vals[j] / 0.6f) : 0.0f;
}

// tf32 tensor-core GEMM: h[128-row blocks] = x @ W
// Block: 128(M) x 128(N) x 16(K-stage), 8 warps, each warp 32x64.
// Smem staged in mma fragment order for conflict-free LDS.
__global__ __launch_bounds__(256, 2)
void gemm_kernel(const float* __restrict__ W) {
  __shared__ unsigned As[2048];   // [kb(2)][mfrag(8)][lane(32)][e(4)]
  __shared__ unsigned Bs[2048];   // [kb(2)][nfrag(16)][lane(32)][e(2)]
  const int tid  = threadIdx.x;
  const int lane = tid & 31;
  const int wid  = tid >> 5;
  const int warp_m = wid & 3;     // 4 M-warps of 32 rows
  const int warp_n = wid >> 2;    // 2 N-warps of 64 cols
  const int m0 = blockIdx.x * 128;

  // A loader: float4 idx tid -> row = tid>>2 (0..63), kq = (tid&3)*4; 2nd f4: row+64
  const int a_row = tid >> 2;
  const int a_kq  = (tid & 3) << 2;
  const int a_kb  = a_kq >> 3;
  const int a_eh  = (a_kq >> 2) & 1;
  const int ar0 = a_row, ar1 = a_row + 64;
  const int as_base0 = ((a_kb * 8 + (ar0 >> 4)) * 32 + (ar0 & 7) * 4) * 4 + a_eh * 2 + ((ar0 >> 3) & 1);
  const int as_base1 = ((a_kb * 8 + (ar1 >> 4)) * 32 + (ar1 & 7) * 4) * 4 + a_eh * 2 + ((ar1 >> 3) & 1);
  const float* aptr0 = g_x + (size_t)(m0 + ar0) * D_IN + a_kq;
  const float* aptr1 = g_x + (size_t)(m0 + ar1) * D_IN + a_kq;
  const bool aok0 = (m0 + ar0) < N_NODES;
  const bool aok1 = (m0 + ar1) < N_NODES;

  // B loader: float4 idx tid -> k = tid>>5 (0..7), n0 = (tid&31)*4; 2nd f4: k+8
  const int b_k  = tid >> 5;
  const int b_n0 = (tid & 31) << 2;
  const int bs_base0 = (((b_k >> 3) * 16 + (b_n0 >> 3)) * 32 + (b_n0 & 7) * 4 + (b_k & 3)) * 2 + ((b_k & 7) >> 2);
  const int bkk = b_k + 8;
  const int bs_base1 = (((bkk >> 3) * 16 + (b_n0 >> 3)) * 32 + (b_n0 & 7) * 4 + (bkk & 3)) * 2 + ((bkk & 7) >> 2);
  const float* bptr0 = W + b_k * D_H + b_n0;
  const float* bptr1 = W + bkk * D_H + b_n0;

  float acc[2][8][4];
#pragma unroll
  for (int mf = 0; mf < 2; mf++)
#pragma unroll
    for (int nf = 0; nf < 8; nf++)
#pragma unroll
      for (int e = 0; e < 4; e++) acc[mf][nf][e] = 0.0f;

  const float4 z4 = make_float4(0.f, 0.f, 0.f, 0.f);
  float4 aR0 = aok0 ? *(const float4*)aptr0 : z4;
  float4 aR1 = aok1 ? *(const float4*)aptr1 : z4;
  float4 bR0 = *(const float4*)bptr0;
  float4 bR1 = *(const float4*)bptr1;

  for (int kt = 0; kt < D_IN / 16; kt++) {
    __syncthreads();
    As[as_base0]      = f2tf32(aR0.x);
    As[as_base0 + 4]  = f2tf32(aR0.y);
    As[as_base0 + 8]  = f2tf32(aR0.z);
    As[as_base0 + 12] = f2tf32(aR0.w);
    As[as_base1]      = f2tf32(aR1.x);
    As[as_base1 + 4]  = f2tf32(aR1.y);
    As[as_base1 + 8]  = f2tf32(aR1.z);
    As[as_base1 + 12] = f2tf32(aR1.w);
    Bs[bs_base0]      = f2tf32(bR0.x);
    Bs[bs_base0 + 8]  = f2tf32(bR0.y);
    Bs[bs_base0 + 16] = f2tf32(bR0.z);
    Bs[bs_base0 + 24] = f2tf32(bR0.w);
    Bs[bs_base1]      = f2tf32(bR1.x);
    Bs[bs_base1 + 8]  = f2tf32(bR1.y);
    Bs[bs_base1 + 16] = f2tf32(bR1.z);
    Bs[bs_base1 + 24] = f2tf32(bR1.w);
    __syncthreads();

    if (kt + 1 < D_IN / 16) {
      int off = (kt + 1) * 16;
      aR0 = aok0 ? *(const float4*)(aptr0 + off) : z4;
      aR1 = aok1 ? *(const float4*)(aptr1 + off) : z4;
      bR0 = *(const float4*)(bptr0 + off * D_H);
      bR1 = *(const float4*)(bptr1 + off * D_H);
    }

#pragma unroll
    for (int kb = 0; kb < 2; kb++) {
      unsigned a[2][4];
#pragma unroll
      for (int mf = 0; mf < 2; mf++)
        *(uint4*)a[mf] = *(const uint4*)&As[((kb * 8 + warp_m * 2 + mf) * 32 + lane) * 4];
#pragma unroll
      for (int nf = 0; nf < 8; nf++) {
        uint2 b = *(const uint2*)&Bs[((kb * 16 + warp_n * 8 + nf) * 32 + lane) * 2];
#pragma unroll
        for (int mf = 0; mf < 2; mf++) {
          asm volatile(
            "mma.sync.aligned.m16n8k8.row.col.f32.tf32.tf32.f32 "
            "{%0,%1,%2,%3}, {%4,%5,%6,%7}, {%8,%9}, {%0,%1,%2,%3};\n"
            : "+f"(acc[mf][nf][0]), "+f"(acc[mf][nf][1]),
              "+f"(acc[mf][nf][2]), "+f"(acc[mf][nf][3])
            : "r"(a[mf][0]), "r"(a[mf][1]), "r"(a[mf][2]), "r"(a[mf][3]),
              "r"(b.x), "r"(b.y));
        }
      }
    }
  }

#pragma unroll
  for (int mf = 0; mf < 2; mf++) {
    int r0 = m0 + (warp_m * 2 + mf) * 16 + (lane >> 2);
#pragma unroll
    for (int nf = 0; nf < 8; nf++) {
      int col = (warp_n * 8 + nf) * 8 + (lane & 3) * 2;
      if (r0 < N_NODES)
        *(float2*)&g_h[(size_t)r0 * D_H + col] =
            make_float2(acc[mf][nf][0], acc[mf][nf][1]);
      if (r0 + 8 < N_NODES)
        *(float2*)&g_h[(size_t)(r0 + 8) * D_H + col] =
            make_float2(acc[mf][nf][2], acc[mf][nf][3]);
    }
  }
}

// 4 edges per warp for MLP
#define EPW 4
__global__ void spmm_kernel(const int* __restrict__ aidx,
                            float* __restrict__ out) {
  int w = (blockIdx.x * blockDim.x + threadIdx.x) >> 5;
  int lane = threadIdx.x & 31;
  int e0 = w * EPW;
  if (e0 >= N_EDGES) return;

  float4 m[EPW];
  int row[EPW];
  bool act[EPW];
#pragma unroll
  for (int i = 0; i < EPW; i++) {
    int e = e0 + i;
    act[i] = false;
    if (e < N_EDGES) {
      float v = g_vals[e];
      if (v != 0.0f) {
        int r = aidx[e];
        int c = aidx[N_EDGES + e];
        if ((unsigned)r < (unsigned)N_NODES && (unsigned)c < (unsigned)N_NODES) {
          float4 t = *((const float4*)(g_h + (size_t)c * D_H) + lane);
          m[i] = make_float4(t.x * v, t.y * v, t.z * v, t.w * v);
          row[i] = r;
          act[i] = true;
        }
      }
    }
  }
#pragma unroll
  for (int i = 0; i < EPW; i++)
    if (act[i])
      atomicAdd(((float4*)(out + (size_t)row[i] * D_H)) + lane, m[i]);
}

__device__ __forceinline__ float elu_f(float a) {
  return a > 0.0f ? a : expm1f(a);
}

__global__ void stats_kernel(const float* __restrict__ agg) {
  int c = threadIdx.x & (D_H - 1);
  int r0 = blockIdx.x * 2 + (threadIdx.x >> 7);
  int stride = gridDim.x * 2;
  float s = 0.0f, s2 = 0.0f;
  for (int r = r0; r < N_NODES; r += stride) {
    float f = elu_f(agg[(size_t)r * D_H + c]);
    s += f;
    s2 = fmaf(f, f, s2);
  }
  atomicAdd(&g_sum[c], (double)s);
  atomicAdd(&g_sumsq[c], (double)s2);
}

__global__ void finalize_params_kernel(const float* __restrict__ gamma,
                                       const float* __restrict__ beta) {
  int c = threadIdx.x;
  float mean = (float)(g_sum[c]   * (1.0 / (double)N_NODES));
  float ex2  = (float)(g_sumsq[c] * (1.0 / (double)N_NODES));
  float var  = ex2 - mean * mean;
  float rs = rsqrtf(var + 1e-5f);
  float sc = gamma[c] * rs;
  g_scale[c] = sc;
  g_shift[c] = fmaf(-mean, sc, beta[c]);
}

__global__ void bn_apply_kernel(float* __restrict__ out) {
  int t = blockIdx.x * blockDim.x + threadIdx.x;
  if (t >= NH / 4) return;
  float4 a = ((float4*)out)[t];
  int c = (t * 4) & (D_H - 1);
  a.x = fmaf(elu_f(a.x), g_scale[c + 0], g_shift[c + 0]);
  a.y = fmaf(elu_f(a.y), g_scale[c + 1], g_shift[c + 1]);
  a.z = fmaf(elu_f(a.z), g_scale[c + 2], g_shift[c + 2]);
  a.w = fmaf(elu_f(a.w), g_scale[c + 3], g_shift[c + 3]);
  ((float4*)out)[t] = a;
}

extern "C" void kernel_launch(void* const* d_in, const int* in_sizes, int n_in,
                              void* d_out, int out_size) {
  const float* data  = (const float*)d_in[0];
  const int*   aidx  = (const int*)d_in[1];     // int32 [2, E]
  const float* avals = (const float*)d_in[2];
  const float* W     = (const float*)d_in[3];
  const float* gamma = (const float*)d_in[4];
  const float* beta  = (const float*)d_in[5];
  float* out = (float*)d_out;

  unsigned keys[4][2];
  for (unsigned j = 0; j < 4; j++) {
    unsigned x0 = 0u, x1 = j;
    tf2x32(0u, 42u, x0, x1);
    keys[j][0] = x0; keys[j][1] = x1;
  }

  cudaMemsetAsync(out, 0, (size_t)NH * sizeof(float), 0);
  zero_stats_kernel<<<1, D_H>>>();
  rng_x_kernel<<<(NX / 4 + 255) / 256, 256>>>(data,
      keys[0][0], keys[0][1], keys[1][0], keys[1][1], keys[2][0], keys[2][1]);
  edge_kernel<<<(N_EDGES + 255) / 256, 256>>>(avals, keys[3][0], keys[3][1]);
  gemm_kernel<<<(N_NODES + 127) / 128, 256>>>(W);
  {
    int warps = (N_EDGES + EPW - 1) / EPW;
    spmm_kernel<<<(warps * 32 + 255) / 256, 256>>>(aidx, out);
  }
  stats_kernel<<<592, 256>>>(out);
  finalize_params_kernel<<<1, D_H>>>(gamma, beta);
  bn_apply_kernel<<<(NH / 4 + 255) / 256, 256>>>(out);
}

// round 12
// speedup vs baseline: 1.1064x; 1.1064x over previous
#include <cuda_runtime.h>
#include <cstdint>

#define N_NODES 100000
#define D_IN    512
#define D_H     128
#define NX      (N_NODES * D_IN)
#define NH      (N_NODES * D_H)
#define N_EDGES 1600000

__device__ __align__(16) float g_x[NX];          // tf32-pre-rounded bits
__device__ __align__(16) float g_h[NH];
__device__ __align__(16) float g_vals[N_EDGES];
__device__ __align__(16) uint2 g_Wf[64 * 16 * 32];  // W in tf32 fragment order
__device__ double g_sum[D_H];
__device__ double g_sumsq[D_H];
__device__ float  g_scale[D_H];
__device__ float  g_shift[D_H];

__host__ __device__ __forceinline__ void tf2x32(unsigned k0, unsigned k1,
                                                unsigned &x0, unsigned &x1) {
  unsigned k2 = k0 ^ k1 ^ 0x1BD11BDAu;
  x0 += k0; x1 += k1;
#define TFR(r) { x0 += x1; x1 = (x1 << (r)) | (x1 >> (32 - (r))); x1 ^= x0; }
  TFR(13) TFR(15) TFR(26) TFR(6)   x0 += k1; x1 += k2 + 1u;
  TFR(17) TFR(29) TFR(16) TFR(24)  x0 += k2; x1 += k0 + 2u;
  TFR(13) TFR(15) TFR(26) TFR(6)   x0 += k0; x1 += k1 + 3u;
  TFR(17) TFR(29) TFR(16) TFR(24)  x0 += k1; x1 += k2 + 4u;
  TFR(13) TFR(15) TFR(26) TFR(6)   x0 += k2; x1 += k0 + 5u;
#undef TFR
}

__device__ __forceinline__ unsigned rbits32(unsigned k0, unsigned k1, unsigned i) {
  unsigned x0 = 0u, x1 = i;
  tf2x32(k0, k1, x0, x1);
  return x0 ^ x1;
}

__device__ __forceinline__ float u01(unsigned b) {
  return __uint_as_float((b >> 9) | 0x3F800000u) - 1.0f;
}

__device__ __forceinline__ float erfinv_xla(float x) {
  float w = -log1pf(-x * x);
  float p;
  if (w < 5.0f) {
    w -= 2.5f;
    p = 2.81022636e-08f;
    p = fmaf(p, w, 3.43273939e-07f);
    p = fmaf(p, w, -3.5233877e-06f);
    p = fmaf(p, w, -4.39150654e-06f);
    p = fmaf(p, w, 0.00021858087f);
    p = fmaf(p, w, -0.00125372503f);
    p = fmaf(p, w, -0.00417768164f);
    p = fmaf(p, w, 0.246640727f);
    p = fmaf(p, w, 1.50140941f);
  } else {
    w = sqrtf(w) - 3.0f;
    p = -0.000200214257f;
    p = fmaf(p, w, 0.000100950558f);
    p = fmaf(p, w, 0.00134934322f);
    p = fmaf(p, w, -0.00367342844f);
    p = fmaf(p, w, 0.00573950773f);
    p = fmaf(p, w, -0.0076224613f);
    p = fmaf(p, w, 0.00943887047f);
    p = fmaf(p, w, 1.00167406f);
    p = fmaf(p, w, 2.83297682f);
  }
  return p * x;
}

__device__ __forceinline__ float normal32(unsigned b) {
  const float LO = -0.99999994f;
  float f = u01(b);
  float u = fmaxf(LO, f * 2.0f + LO);
  return 1.4142135381698608f * erfinv_xla(u);
}

__device__ __forceinline__ unsigned f2tf32(float f) {
  unsigned r;
  asm("cvt.rna.tf32.f32 %0, %1;" : "=r"(r) : "f"(f));
  return r;
}

__global__ void zero_stats_kernel() {
  g_sum[threadIdx.x] = 0.0;
  g_sumsq[threadIdx.x] = 0.0;
}

// W -> tf32 fragment order: [k8(64)][nf(16)][lane(32)]{b0,b1}
// b0 = W[k8*8+(l&3)][nf*8+(l>>2)], b1 = W[k8*8+(l&3)+4][same n]
__global__ void wprep_kernel(const float* __restrict__ W) {
  int t = blockIdx.x * blockDim.x + threadIdx.x;
  if (t >= 64 * 16 * 32) return;
  int lane = t & 31, nf = (t >> 5) & 15, k8 = t >> 9;
  int k = k8 * 8 + (lane & 3);
  int n = nf * 8 + (lane >> 2);
  g_Wf[t] = make_uint2(f2tf32(W[k * D_H + n]), f2tf32(W[(k + 4) * D_H + n]));
}

// noise + 2 dropouts, output stored as tf32-rounded bits
__global__ void rng_x_kernel(const float* __restrict__ data,
                             unsigned kn0, unsigned kn1,
                             unsigned ka0, unsigned ka1,
                             unsigned kb0, unsigned kb1) {
  int t = blockIdx.x * blockDim.x + threadIdx.x;
  if (t >= NX / 4) return;
  int base = t * 4;
  float4 d = *((const float4*)data + t);
  float dv[4] = {d.x, d.y, d.z, d.w};
  float o[4];
#pragma unroll
  for (int e = 0; e < 4; e++) {
    unsigned i = (unsigned)(base + e);
    unsigned b1 = rbits32(ka0, ka1, i);
    unsigned b2 = rbits32(kb0, kb1, i);
    if (((b1 | b2) & 0x80000000u) == 0u) {
      float n = normal32(rbits32(kn0, kn1, i));
      o[e] = __uint_as_float(f2tf32((dv[e] + 0.01f * n) * 4.0f));
    } else {
      o[e] = 0.0f;
    }
  }
  *((float4*)g_x + t) = make_float4(o[0], o[1], o[2], o[3]);
}

__global__ void edge_kernel(const float* __restrict__ adj_vals,
                            unsigned ke0, unsigned ke1) {
  int j = blockIdx.x * blockDim.x + threadIdx.x;
  if (j >= N_EDGES) return;
  unsigned b = rbits32(ke0, ke1, (unsigned)j);
  g_vals[j] = (u01(b) < 0.6f) ? (adj_vals[j] / 0.6f) : 0.0f;
}

// tf32 MMA GEMM, no shared memory: A frags LDG from g_x (pre-rounded),
// B frags LDG.64 from g_Wf (fragment order, L2-resident).
// Block = 128M x 128N, 8 warps: warp = 32M x 64N.
__global__ __launch_bounds__(256)
void gemm_kernel() {
  const int tid  = threadIdx.x;
  const int lane = tid & 31;
  const int wid  = tid >> 5;
  const int warp_m = wid & 3;
  const int warp_n = wid >> 2;
  const int m0 = blockIdx.x * 128;

  const unsigned* xb = (const unsigned*)g_x;
  // per-mf base row and pointer
  int r0 = m0 + warp_m * 32 + (lane >> 2);        // mf=0 row
  int r1 = r0 + 16;                               // mf=1 row
  const unsigned* pa0 = xb + (size_t)r0 * D_IN + (lane & 3);
  const unsigned* pa1 = xb + (size_t)r1 * D_IN + (lane & 3);
  const bool ok0a = r0 < N_NODES,     ok0b = (r0 + 8) < N_NODES;
  const bool ok1a = r1 < N_NODES,     ok1b = (r1 + 8) < N_NODES;
  const uint2* pb = g_Wf + (size_t)warp_n * 8 * 32 + lane;

  float acc[2][8][4];
#pragma unroll
  for (int mf = 0; mf < 2; mf++)
#pragma unroll
    for (int nf = 0; nf < 8; nf++)
#pragma unroll
      for (int e = 0; e < 4; e++) acc[mf][nf][e] = 0.0f;

#pragma unroll 2
  for (int k8 = 0; k8 < 64; k8++) {
    const int ko = k8 * 8;
    unsigned a[2][4];
    a[0][0] = ok0a ? pa0[ko]               : 0u;
    a[0][1] = ok0b ? pa0[ko + 8 * D_IN]     : 0u;
    a[0][2] = ok0a ? pa0[ko + 4]            : 0u;
    a[0][3] = ok0b ? pa0[ko + 8 * D_IN + 4] : 0u;
    a[1][0] = ok1a ? pa1[ko]               : 0u;
    a[1][1] = ok1b ? pa1[ko + 8 * D_IN]     : 0u;
    a[1][2] = ok1a ? pa1[ko + 4]            : 0u;
    a[1][3] = ok1b ? pa1[ko + 8 * D_IN + 4] : 0u;
    uint2 b[8];
#pragma unroll
    for (int nf = 0; nf < 8; nf++)
      b[nf] = pb[((size_t)k8 * 16 + nf) * 32];
#pragma unroll
    for (int nf = 0; nf < 8; nf++) {
#pragma unroll
      for (int mf = 0; mf < 2; mf++) {
        asm volatile(
          "mma.sync.aligned.m16n8k8.row.col.f32.tf32.tf32.f32 "
          "{%0,%1,%2,%3}, {%4,%5,%6,%7}, {%8,%9}, {%0,%1,%2,%3};\n"
          : "+f"(acc[mf][nf][0]), "+f"(acc[mf][nf][1]),
            "+f"(acc[mf][nf][2]), "+f"(acc[mf][nf][3])
          : "r"(a[mf][0]), "r"(a[mf][1]), "r"(a[mf][2]), "r"(a[mf][3]),
            "r"(b[nf].x), "r"(b[nf].y));
      }
    }
  }

#pragma unroll
  for (int mf = 0; mf < 2; mf++) {
    int r = m0 + warp_m * 32 + mf * 16 + (lane >> 2);
#pragma unroll
    for (int nf = 0; nf < 8; nf++) {
      int col = (warp_n * 8 + nf) * 8 + (lane & 3) * 2;
      if (r < N_NODES)
        *(float2*)&g_h[(size_t)r * D_H + col] =
            make_float2(acc[mf][nf][0], acc[mf][nf][1]);
      if (r + 8 < N_NODES)
        *(float2*)&g_h[(size_t)(r + 8) * D_H + col] =
            make_float2(acc[mf][nf][2], acc[mf][nf][3]);
    }
  }
}

// 4 edges per warp for MLP
#define EPW 4
__global__ void spmm_kernel(const int* __restrict__ aidx,
                            float* __restrict__ out) {
  int w = (blockIdx.x * blockDim.x + threadIdx.x) >> 5;
  int lane = threadIdx.x & 31;
  int e0 = w * EPW;
  if (e0 >= N_EDGES) return;

  float4 m[EPW];
  int row[EPW];
  bool act[EPW];
#pragma unroll
  for (int i = 0; i < EPW; i++) {
    int e = e0 + i;
    act[i] = false;
    if (e < N_EDGES) {
      float v = g_vals[e];
      if (v != 0.0f) {
        int r = aidx[e];
        int c = aidx[N_EDGES + e];
        if ((unsigned)r < (unsigned)N_NODES && (unsigned)c < (unsigned)N_NODES) {
          float4 t = *((const float4*)(g_h + (size_t)c * D_H) + lane);
          m[i] = make_float4(t.x * v, t.y * v, t.z * v, t.w * v);
          row[i] = r;
          act[i] = true;
        }
      }
    }
  }
#pragma unroll
  for (int i = 0; i < EPW; i++)
    if (act[i])
      atomicAdd(((float4*)(out + (size_t)row[i] * D_H)) + lane, m[i]);
}

__device__ __forceinline__ float elu_f(float a) {
  return a > 0.0f ? a : expm1f(a);
}

__global__ void stats_kernel(const float* __restrict__ agg) {
  int c = threadIdx.x & (D_H - 1);
  int r0 = blockIdx.x * 2 + (threadIdx.x >> 7);
  int stride = gridDim.x * 2;
  float s = 0.0f, s2 = 0.0f;
  for (int r = r0; r < N_NODES; r += stride) {
    float f = elu_f(agg[(size_t)r * D_H + c]);
    s += f;
    s2 = fmaf(f, f, s2);
  }
  atomicAdd(&g_sum[c], (double)s);
  atomicAdd(&g_sumsq[c], (double)s2);
}

__global__ void finalize_params_kernel(const float* __restrict__ gamma,
                                       const float* __restrict__ beta) {
  int c = threadIdx.x;
  float mean = (float)(g_sum[c]   * (1.0 / (double)N_NODES));
  float ex2  = (float)(g_sumsq[c] * (1.0 / (double)N_NODES));
  float var  = ex2 - mean * mean;
  float rs = rsqrtf(var + 1e-5f);
  float sc = gamma[c] * rs;
  g_scale[c] = sc;
  g_shift[c] = fmaf(-mean, sc, beta[c]);
}

__global__ void bn_apply_kernel(float* __restrict__ out) {
  int t = blockIdx.x * blockDim.x + threadIdx.x;
  if (t >= NH / 4) return;
  float4 a = ((float4*)out)[t];
  int c = (t * 4) & (D_H - 1);
  a.x = fmaf(elu_f(a.x), g_scale[c + 0], g_shift[c + 0]);
  a.y = fmaf(elu_f(a.y), g_scale[c + 1], g_shift[c + 1]);
  a.z = fmaf(elu_f(a.z), g_scale[c + 2], g_shift[c + 2]);
  a.w = fmaf(elu_f(a.w), g_scale[c + 3], g_shift[c + 3]);
  ((float4*)out)[t] = a;
}

extern "C" void kernel_launch(void* const* d_in, const int* in_sizes, int n_in,
                              void* d_out, int out_size) {
  const float* data  = (const float*)d_in[0];
  const int*   aidx  = (const int*)d_in[1];     // int32 [2, E]
  const float* avals = (const float*)d_in[2];
  const float* W     = (const float*)d_in[3];
  const float* gamma = (const float*)d_in[4];
  const float* beta  = (const float*)d_in[5];
  float* out = (float*)d_out;

  unsigned keys[4][2];
  for (unsigned j = 0; j < 4; j++) {
    unsigned x0 = 0u, x1 = j;
    tf2x32(0u, 42u, x0, x1);
    keys[j][0] = x0; keys[j][1] = x1;
  }

  cudaMemsetAsync(out, 0, (size_t)NH * sizeof(float), 0);
  zero_stats_kernel<<<1, D_H>>>();
  wprep_kernel<<<(64 * 16 * 32 + 255) / 256, 256>>>(W);
  rng_x_kernel<<<(NX / 4 + 255) / 256, 256>>>(data,
      keys[0][0], keys[0][1], keys[1][0], keys[1][1], keys[2][0], keys[2][1]);
  edge_kernel<<<(N_EDGES + 255) / 256, 256>>>(avals, keys[3][0], keys[3][1]);
  gemm_kernel<<<(N_NODES + 127) / 128, 256>>>();
  {
    int warps = (N_EDGES + EPW - 1) / EPW;
    spmm_kernel<<<(warps * 32 + 255) / 256, 256>>>(aidx, out);
  }
  stats_kernel<<<592, 256>>>(out);
  finalize_params_kernel<<<1, D_H>>>(gamma, beta);
  bn_apply_kernel<<<(NH / 4 + 255) / 256, 256>>>(out);
}

// round 15
// speedup vs baseline: 1.1184x; 1.0109x over previous
#include <cuda_runtime.h>
#include <cstdint>

#define N_NODES 100000
#define D_IN    512
#define D_H     128
#define NH      (N_NODES * D_H)
#define N_EDGES 1600000

__device__ __align__(16) float g_h[NH];
__device__ __align__(16) float g_vals[N_EDGES];
__device__ __align__(16) uint2 g_Wf[64 * 16 * 32];  // W in tf32 fragment order
__device__ double g_sum[D_H];
__device__ double g_sumsq[D_H];
__device__ float  g_scale[D_H];
__device__ float  g_shift[D_H];

__host__ __device__ __forceinline__ void tf2x32(unsigned k0, unsigned k1,
                                                unsigned &x0, unsigned &x1) {
  unsigned k2 = k0 ^ k1 ^ 0x1BD11BDAu;
  x0 += k0; x1 += k1;
#define TFR(r) { x0 += x1; x1 = (x1 << (r)) | (x1 >> (32 - (r))); x1 ^= x0; }
  TFR(13) TFR(15) TFR(26) TFR(6)   x0 += k1; x1 += k2 + 1u;
  TFR(17) TFR(29) TFR(16) TFR(24)  x0 += k2; x1 += k0 + 2u;
  TFR(13) TFR(15) TFR(26) TFR(6)   x0 += k0; x1 += k1 + 3u;
  TFR(17) TFR(29) TFR(16) TFR(24)  x0 += k1; x1 += k2 + 4u;
  TFR(13) TFR(15) TFR(26) TFR(6)   x0 += k2; x1 += k0 + 5u;
#undef TFR
}

__device__ __forceinline__ unsigned rbits32(unsigned k0, unsigned k1, unsigned i) {
  unsigned x0 = 0u, x1 = i;
  tf2x32(k0, k1, x0, x1);
  return x0 ^ x1;
}

__device__ __forceinline__ float u01(unsigned b) {
  return __uint_as_float((b >> 9) | 0x3F800000u) - 1.0f;
}

__device__ __forceinline__ float erfinv_fast(float x) {
  // -log1p(-x*x) == -log(1-x*x); fma keeps the residual exact, __logf ~2ulp.
  // Error feeds a *0.04 additive noise term: invisible at 1e-3 tolerance.
  float w = -__logf(fmaf(-x, x, 1.0f));
  float p;
  if (w < 5.0f) {
    w -= 2.5f;
    p = 2.81022636e-08f;
    p = fmaf(p, w, 3.43273939e-07f);
    p = fmaf(p, w, -3.5233877e-06f);
    p = fmaf(p, w, -4.39150654e-06f);
    p = fmaf(p, w, 0.00021858087f);
    p = fmaf(p, w, -0.00125372503f);
    p = fmaf(p, w, -0.00417768164f);
    p = fmaf(p, w, 0.246640727f);
    p = fmaf(p, w, 1.50140941f);
  } else {
    w = sqrtf(w) - 3.0f;
    p = -0.000200214257f;
    p = fmaf(p, w, 0.000100950558f);
    p = fmaf(p, w, 0.00134934322f);
    p = fmaf(p, w, -0.00367342844f);
    p = fmaf(p, w, 0.00573950773f);
    p = fmaf(p, w, -0.0076224613f);
    p = fmaf(p, w, 0.00943887047f);
    p = fmaf(p, w, 1.00167406f);
    p = fmaf(p, w, 2.83297682f);
  }
  return p * x;
}

__device__ __forceinline__ float normal32(unsigned b) {
  const float LO = -0.99999994f;
  float f = u01(b);
  float u = fmaxf(LO, f * 2.0f + LO);
  return 1.4142135381698608f * erfinv_fast(u);
}

__device__ __forceinline__ unsigned f2tf32(float f) {
  unsigned r;
  asm("cvt.rna.tf32.f32 %0, %1;" : "=r"(r) : "f"(f));
  return r;
}

// noise + both dropouts for one element, returns tf32 bits of x (or 0)
__device__ __forceinline__ unsigned gen_x_tf32(float dv, unsigned i,
                                               unsigned kn0, unsigned kn1,
                                               unsigned ka0, unsigned ka1,
                                               unsigned kb0, unsigned kb1) {
  unsigned b1 = rbits32(ka0, ka1, i);
  unsigned b2 = rbits32(kb0, kb1, i);
  unsigned r = 0u;
  if (((b1 | b2) & 0x80000000u) == 0u) {
    float n = normal32(rbits32(kn0, kn1, i));
    r = f2tf32((dv + 0.01f * n) * 4.0f);
  }
  return r;
}

__global__ void zero_stats_kernel() {
  g_sum[threadIdx.x] = 0.0;
  g_sumsq[threadIdx.x] = 0.0;
}

// W -> tf32 fragment order: [k8(64)][nf(16)][lane(32)]{b0,b1}
__global__ void wprep_kernel(const float* __restrict__ W) {
  int t = blockIdx.x * blockDim.x + threadIdx.x;
  if (t >= 64 * 16 * 32) return;
  int lane = t & 31, nf = (t >> 5) & 15, k8 = t >> 9;
  int k = k8 * 8 + (lane & 3);
  int n = nf * 8 + (lane >> 2);
  g_Wf[t] = make_uint2(f2tf32(W[k * D_H + n]), f2tf32(W[(k + 4) * D_H + n]));
}

__global__ void edge_kernel(const float* __restrict__ adj_vals,
                            unsigned ke0, unsigned ke1) {
  int j = blockIdx.x * blockDim.x + threadIdx.x;
  if (j >= N_EDGES) return;
  unsigned b = rbits32(ke0, ke1, (unsigned)j);
  g_vals[j] = (u01(b) < 0.6f) ? (adj_vals[j] / 0.6f) : 0.0f;
}

// Fused RNG + tf32 MMA GEMM, no smem, no barriers.
// Block = 128 rows; warp = 16 rows x 128 N  =>  each A element RNG'd exactly once.
// Per k8: 4 data LDG + 4 gen_x (alu, overlaps other warps' MMAs) + 16 B LDG.64 (L1) + 16 MMA.
__global__ __launch_bounds__(256)
void gemm_rng_kernel(const float* __restrict__ data,
                     unsigned kn0, unsigned kn1,
                     unsigned ka0, unsigned ka1,
                     unsigned kb0, unsigned kb1) {
  const int lane = threadIdx.x & 31;
  const int wid  = threadIdx.x >> 5;
  const int m0   = blockIdx.x * 128;
  const int r0 = m0 + wid * 16 + (lane >> 2);   // rows for a0/a2
  const int r1 = r0 + 8;                        // rows for a1/a3
  const int q  = lane & 3;
  const bool ok0 = r0 < N_NODES;
  const bool ok1 = r1 < N_NODES;
  const float* p0 = data + (size_t)r0 * D_IN + q;
  const float* p1 = data + (size_t)r1 * D_IN + q;
  const unsigned i0 = (unsigned)r0 * D_IN + (unsigned)q;
  const unsigned i1 = (unsigned)r1 * D_IN + (unsigned)q;
  const uint2* pb = g_Wf + lane;

  float acc[16][4];
#pragma unroll
  for (int nf = 0; nf < 16; nf++)
#pragma unroll
    for (int e = 0; e < 4; e++) acc[nf][e] = 0.0f;

  for (int k8 = 0; k8 < 64; k8++) {
    const int ko = k8 * 8;
    float d0 = ok0 ? p0[ko]     : 0.0f;
    float d1 = ok1 ? p1[ko]     : 0.0f;
    float d2 = ok0 ? p0[ko + 4] : 0.0f;
    float d3 = ok1 ? p1[ko + 4] : 0.0f;
    unsigned a0 = ok0 ? gen_x_tf32(d0, i0 + ko,     kn0,kn1, ka0,ka1, kb0,kb1) : 0u;
    unsigned a1 = ok1 ? gen_x_tf32(d1, i1 + ko,     kn0,kn1, ka0,ka1, kb0,kb1) : 0u;
    unsigned a2 = ok0 ? gen_x_tf32(d2, i0 + ko + 4, kn0,kn1, ka0,ka1, kb0,kb1) : 0u;
    unsigned a3 = ok1 ? gen_x_tf32(d3, i1 + ko + 4, kn0,kn1, ka0,ka1, kb0,kb1) : 0u;
#pragma unroll
    for (int nf = 0; nf < 16; nf++) {
      uint2 b = pb[((size_t)k8 * 16 + nf) * 32];
      asm volatile(
        "mma.sync.aligned.m16n8k8.row.col.f32.tf32.tf32.f32 "
        "{%0,%1,%2,%3}, {%4,%5,%6,%7}, {%8,%9}, {%0,%1,%2,%3};\n"
        : "+f"(acc[nf][0]), "+f"(acc[nf][1]),
          "+f"(acc[nf][2]), "+f"(acc[nf][3])
        : "r"(a0), "r"(a1), "r"(a2), "r"(a3),
          "r"(b.x), "r"(b.y));
    }
  }

#pragma unroll
  for (int nf = 0; nf < 16; nf++) {
    int col = nf * 8 + (lane & 3) * 2;
    if (ok0)
      *(float2*)&g_h[(size_t)r0 * D_H + col] = make_float2(acc[nf][0], acc[nf][1]);
    if (ok1)
      *(float2*)&g_h[(size_t)r1 * D_H + col] = make_float2(acc[nf][2], acc[nf][3]);
  }
}

// 4 edges per warp for MLP
#define EPW 4
__global__ void spmm_kernel(const int* __restrict__ aidx,
                            float* __restrict__ out) {
  int w = (blockIdx.x * blockDim.x + threadIdx.x) >> 5;
  int lane = threadIdx.x & 31;
  int e0 = w * EPW;
  if (e0 >= N_EDGES) return;

  float4 m[EPW];
  int row[EPW];
  bool act[EPW];
#pragma unroll
  for (int i = 0; i < EPW; i++) {
    int e = e0 + i;
    act[i] = false;
    if (e < N_EDGES) {
      float v = g_vals[e];
      if (v != 0.0f) {
        int r = aidx[e];
        int c = aidx[N_EDGES + e];
        if ((unsigned)r < (unsigned)N_NODES && (unsigned)c < (unsigned)N_NODES) {
          float4 t = *((const float4*)(g_h + (size_t)c * D_H) + lane);
          m[i] = make_float4(t.x * v, t.y * v, t.z * v, t.w * v);
          row[i] = r;
          act[i] = true;
        }
      }
    }
  }
#pragma unroll
  for (int i = 0; i < EPW; i++)
    if (act[i])
      atomicAdd(((float4*)(out + (size_t)row[i] * D_H)) + lane, m[i]);
}

__device__ __forceinline__ float elu_f(float a) {
  return a > 0.0f ? a : expm1f(a);
}

__global__ void stats_kernel(const float* __restrict__ agg) {
  int c = threadIdx.x & (D_H - 1);
  int r0 = blockIdx.x * 2 + (threadIdx.x >> 7);
  int stride = gridDim.x * 2;
  float s = 0.0f, s2 = 0.0f;
  for (int r = r0; r < N_NODES; r += stride) {
    float f = elu_f(agg[(size_t)r * D_H + c]);
    s += f;
    s2 = fmaf(f, f, s2);
  }
  atomicAdd(&g_sum[c], (double)s);
  atomicAdd(&g_sumsq[c], (double)s2);
}

__global__ void finalize_params_kernel(const float* __restrict__ gamma,
                                       const float* __restrict__ beta) {
  int c = threadIdx.x;
  float mean = (float)(g_sum[c]   * (1.0 / (double)N_NODES));
  float ex2  = (float)(g_sumsq[c] * (1.0 / (double)N_NODES));
  float var  = ex2 - mean * mean;
  float rs = rsqrtf(var + 1e-5f);
  float sc = gamma[c] * rs;
  g_scale[c] = sc;
  g_shift[c] = fmaf(-mean, sc, beta[c]);
}

__global__ void bn_apply_kernel(float* __restrict__ out) {
  int t = blockIdx.x * blockDim.x + threadIdx.x;
  if (t >= NH / 4) return;
  float4 a = ((float4*)out)[t];
  int c = (t * 4) & (D_H - 1);
  a.x = fmaf(elu_f(a.x), g_scale[c + 0], g_shift[c + 0]);
  a.y = fmaf(elu_f(a.y), g_scale[c + 1], g_shift[c + 1]);
  a.z = fmaf(elu_f(a.z), g_scale[c + 2], g_shift[c + 2]);
  a.w = fmaf(elu_f(a.w), g_scale[c + 3], g_shift[c + 3]);
  ((float4*)out)[t] = a;
}

extern "C" void kernel_launch(void* const* d_in, const int* in_sizes, int n_in,
                              void* d_out, int out_size) {
  const float* data  = (const float*)d_in[0];
  const int*   aidx  = (const int*)d_in[1];     // int32 [2, E]
  const float* avals = (const float*)d_in[2];
  const float* W     = (const float*)d_in[3];
  const float* gamma = (const float*)d_in[4];
  const float* beta  = (const float*)d_in[5];
  float* out = (float*)d_out;

  unsigned keys[4][2];
  for (unsigned j = 0; j < 4; j++) {
    unsigned x0 = 0u, x1 = j;
    tf2x32(0u, 42u, x0, x1);
    keys[j][0] = x0; keys[j][1] = x1;
  }

  cudaMemsetAsync(out, 0, (size_t)NH * sizeof(float), 0);
  zero_stats_kernel<<<1, D_H>>>();
  wprep_kernel<<<(64 * 16 * 32 + 255) / 256, 256>>>(W);
  edge_kernel<<<(N_EDGES + 255) / 256, 256>>>(avals, keys[3][0], keys[3][1]);
  gemm_rng_kernel<<<(N_NODES + 127) / 128, 256>>>(data,
      keys[0][0], keys[0][1], keys[1][0], keys[1][1], keys[2][0], keys[2][1]);
  {
    int warps = (N_EDGES + EPW - 1) / EPW;
    spmm_kernel<<<(warps * 32 + 255) / 256, 256>>>(aidx, out);
  }
  stats_kernel<<<592, 256>>>(out);
  finalize_params_kernel<<<1, D_H>>>(gamma, beta);
  bn_apply_kernel<<<(NH / 4 + 255) / 256, 256>>>(out);
}

// round 16
// speedup vs baseline: 1.2250x; 1.0953x over previous
#include <cuda_runtime.h>
#include <cstdint>

#define N_NODES 100000
#define D_IN    512
#define D_H     128
#define NH      (N_NODES * D_H)
#define N_EDGES 1600000

__device__ __align__(16) float g_h[NH];
__device__ __align__(16) uint2 g_Wf[64 * 16 * 32];  // W in tf32 fragment order
__device__ double g_sum[D_H];
__device__ double g_sumsq[D_H];
__device__ float  g_scale[D_H];
__device__ float  g_shift[D_H];

__host__ __device__ __forceinline__ void tf2x32(unsigned k0, unsigned k1,
                                                unsigned &x0, unsigned &x1) {
  unsigned k2 = k0 ^ k1 ^ 0x1BD11BDAu;
  x0 += k0; x1 += k1;
#define TFR(r) { x0 += x1; x1 = (x1 << (r)) | (x1 >> (32 - (r))); x1 ^= x0; }
  TFR(13) TFR(15) TFR(26) TFR(6)   x0 += k1; x1 += k2 + 1u;
  TFR(17) TFR(29) TFR(16) TFR(24)  x0 += k2; x1 += k0 + 2u;
  TFR(13) TFR(15) TFR(26) TFR(6)   x0 += k0; x1 += k1 + 3u;
  TFR(17) TFR(29) TFR(16) TFR(24)  x0 += k1; x1 += k2 + 4u;
  TFR(13) TFR(15) TFR(26) TFR(6)   x0 += k2; x1 += k0 + 5u;
#undef TFR
}

__device__ __forceinline__ unsigned rbits32(unsigned k0, unsigned k1, unsigned i) {
  unsigned x0 = 0u, x1 = i;
  tf2x32(k0, k1, x0, x1);
  return x0 ^ x1;
}

__device__ __forceinline__ float u01(unsigned b) {
  return __uint_as_float((b >> 9) | 0x3F800000u) - 1.0f;
}

__device__ __forceinline__ float erfinv_fast(float x) {
  float w = -__logf(fmaf(-x, x, 1.0f));
  float p;
  if (w < 5.0f) {
    w -= 2.5f;
    p = 2.81022636e-08f;
    p = fmaf(p, w, 3.43273939e-07f);
    p = fmaf(p, w, -3.5233877e-06f);
    p = fmaf(p, w, -4.39150654e-06f);
    p = fmaf(p, w, 0.00021858087f);
    p = fmaf(p, w, -0.00125372503f);
    p = fmaf(p, w, -0.00417768164f);
    p = fmaf(p, w, 0.246640727f);
    p = fmaf(p, w, 1.50140941f);
  } else {
    w = sqrtf(w) - 3.0f;
    p = -0.000200214257f;
    p = fmaf(p, w, 0.000100950558f);
    p = fmaf(p, w, 0.00134934322f);
    p = fmaf(p, w, -0.00367342844f);
    p = fmaf(p, w, 0.00573950773f);
    p = fmaf(p, w, -0.0076224613f);
    p = fmaf(p, w, 0.00943887047f);
    p = fmaf(p, w, 1.00167406f);
    p = fmaf(p, w, 2.83297682f);
  }
  return p * x;
}

__device__ __forceinline__ float normal32(unsigned b) {
  const float LO = -0.99999994f;
  float f = u01(b);
  float u = fmaxf(LO, f * 2.0f + LO);
  return 1.4142135381698608f * erfinv_fast(u);
}

__device__ __forceinline__ unsigned f2tf32(float f) {
  unsigned r;
  asm("cvt.rna.tf32.f32 %0, %1;" : "=r"(r) : "f"(f));
  return r;
}

__device__ __forceinline__ unsigned gen_x_tf32(float dv, unsigned i,
                                               unsigned kn0, unsigned kn1,
                                               unsigned ka0, unsigned ka1,
                                               unsigned kb0, unsigned kb1) {
  unsigned b1 = rbits32(ka0, ka1, i);
  unsigned b2 = rbits32(kb0, kb1, i);
  unsigned r = 0u;
  if (((b1 | b2) & 0x80000000u) == 0u) {
    float n = normal32(rbits32(kn0, kn1, i));
    r = f2tf32((dv + 0.01f * n) * 4.0f);
  }
  return r;
}

__global__ void zero_stats_kernel() {
  g_sum[threadIdx.x] = 0.0;
  g_sumsq[threadIdx.x] = 0.0;
}

// W -> tf32 fragment order: [k8(64)][nf(16)][lane(32)]{b0,b1}
__global__ void wprep_kernel(const float* __restrict__ W) {
  int t = blockIdx.x * blockDim.x + threadIdx.x;
  if (t >= 64 * 16 * 32) return;
  int lane = t & 31, nf = (t >> 5) & 15, k8 = t >> 9;
  int k = k8 * 8 + (lane & 3);
  int n = nf * 8 + (lane >> 2);
  g_Wf[t] = make_uint2(f2tf32(W[k * D_H + n]), f2tf32(W[(k + 4) * D_H + n]));
}

// Fused RNG + tf32 MMA GEMM, no smem, no barriers.
// Warp = 16 rows x 128 N => each A element RNG'd exactly once.
// All 16 B-fragment loads are issued BEFORE the RNG compute so the
// ~400-cycle ALU phase covers their L2 latency.
__global__ __launch_bounds__(256, 2)
void gemm_rng_kernel(const float* __restrict__ data,
                     unsigned kn0, unsigned kn1,
                     unsigned ka0, unsigned ka1,
                     unsigned kb0, unsigned kb1) {
  const int lane = threadIdx.x & 31;
  const int wid  = threadIdx.x >> 5;
  const int m0   = blockIdx.x * 128;
  const int r0 = m0 + wid * 16 + (lane >> 2);
  const int r1 = r0 + 8;
  const int q  = lane & 3;
  const bool ok0 = r0 < N_NODES;
  const bool ok1 = r1 < N_NODES;
  const float* p0 = data + (size_t)r0 * D_IN + q;
  const float* p1 = data + (size_t)r1 * D_IN + q;
  const unsigned i0 = (unsigned)r0 * D_IN + (unsigned)q;
  const unsigned i1 = (unsigned)r1 * D_IN + (unsigned)q;
  const uint2* pb = g_Wf + lane;

  float acc[16][4];
#pragma unroll
  for (int nf = 0; nf < 16; nf++)
#pragma unroll
    for (int e = 0; e < 4; e++) acc[nf][e] = 0.0f;

  for (int k8 = 0; k8 < 64; k8++) {
    const int ko = k8 * 8;
    // data loads (latency covered: dv used only at end of gen_x)
    float d0 = ok0 ? p0[ko]     : 0.0f;
    float d1 = ok1 ? p1[ko]     : 0.0f;
    float d2 = ok0 ? p0[ko + 4] : 0.0f;
    float d3 = ok1 ? p1[ko + 4] : 0.0f;
    // all B fragments up front — RNG below hides their L2 latency
    uint2 b[16];
#pragma unroll
    for (int nf = 0; nf < 16; nf++)
      b[nf] = pb[((size_t)k8 * 16 + nf) * 32];
    unsigned a0 = ok0 ? gen_x_tf32(d0, i0 + ko,     kn0,kn1, ka0,ka1, kb0,kb1) : 0u;
    unsigned a1 = ok1 ? gen_x_tf32(d1, i1 + ko,     kn0,kn1, ka0,ka1, kb0,kb1) : 0u;
    unsigned a2 = ok0 ? gen_x_tf32(d2, i0 + ko + 4, kn0,kn1, ka0,ka1, kb0,kb1) : 0u;
    unsigned a3 = ok1 ? gen_x_tf32(d3, i1 + ko + 4, kn0,kn1, ka0,ka1, kb0,kb1) : 0u;
#pragma unroll
    for (int nf = 0; nf < 16; nf++) {
      asm volatile(
        "mma.sync.aligned.m16n8k8.row.col.f32.tf32.tf32.f32 "
        "{%0,%1,%2,%3}, {%4,%5,%6,%7}, {%8,%9}, {%0,%1,%2,%3};\n"
        : "+f"(acc[nf][0]), "+f"(acc[nf][1]),
          "+f"(acc[nf][2]), "+f"(acc[nf][3])
        : "r"(a0), "r"(a1), "r"(a2), "r"(a3),
          "r"(b[nf].x), "r"(b[nf].y));
    }
  }

#pragma unroll
  for (int nf = 0; nf < 16; nf++) {
    int col = nf * 8 + (lane & 3) * 2;
    if (ok0)
      *(float2*)&g_h[(size_t)r0 * D_H + col] = make_float2(acc[nf][0], acc[nf][1]);
    if (ok1)
      *(float2*)&g_h[(size_t)r1 * D_H + col] = make_float2(acc[nf][2], acc[nf][3]);
  }
}

// 4 edges per warp; edge dropout fused (lanes 0-3 hash, shfl to all)
#define EPW 4
__global__ void spmm_kernel(const int* __restrict__ aidx,
                            const float* __restrict__ adj_vals,
                            float* __restrict__ out,
                            unsigned ke0, unsigned ke1) {
  int w = (blockIdx.x * blockDim.x + threadIdx.x) >> 5;
  int lane = threadIdx.x & 31;
  int e0 = w * EPW;
  if (e0 >= N_EDGES) return;

  float vv = 0.0f;
  int el = e0 + lane;
  if (lane < EPW && el < N_EDGES) {
    unsigned b = rbits32(ke0, ke1, (unsigned)el);
    vv = (u01(b) < 0.6f) ? (adj_vals[el] / 0.6f) : 0.0f;
  }

  float4 m[EPW];
  int row[EPW];
  bool act[EPW];
#pragma unroll
  for (int i = 0; i < EPW; i++) {
    int e = e0 + i;
    float v = __shfl_sync(0xffffffffu, vv, i);
    act[i] = false;
    if (e < N_EDGES && v != 0.0f) {
      int r = aidx[e];
      int c = aidx[N_EDGES + e];
      if ((unsigned)r < (unsigned)N_NODES && (unsigned)c < (unsigned)N_NODES) {
        float4 t = *((const float4*)(g_h + (size_t)c * D_H) + lane);
        m[i] = make_float4(t.x * v, t.y * v, t.z * v, t.w * v);
        row[i] = r;
        act[i] = true;
      }
    }
  }
#pragma unroll
  for (int i = 0; i < EPW; i++)
    if (act[i])
      atomicAdd(((float4*)(out + (size_t)row[i] * D_H)) + lane, m[i]);
}

__device__ __forceinline__ float elu_f(float a) {
  return a > 0.0f ? a : expm1f(a);
}

__global__ void stats_kernel(const float* __restrict__ agg) {
  int c = threadIdx.x & (D_H - 1);
  int r0 = blockIdx.x * 2 + (threadIdx.x >> 7);
  int stride = gridDim.x * 2;
  float s = 0.0f, s2 = 0.0f;
  for (int r = r0; r < N_NODES; r += stride) {
    float f = elu_f(agg[(size_t)r * D_H + c]);
    s += f;
    s2 = fmaf(f, f, s2);
  }
  atomicAdd(&g_sum[c], (double)s);
  atomicAdd(&g_sumsq[c], (double)s2);
}

__global__ void finalize_params_kernel(const float* __restrict__ gamma,
                                       const float* __restrict__ beta) {
  int c = threadIdx.x;
  float mean = (float)(g_sum[c]   * (1.0 / (double)N_NODES));
  float ex2  = (float)(g_sumsq[c] * (1.0 / (double)N_NODES));
  float var  = ex2 - mean * mean;
  float rs = rsqrtf(var + 1e-5f);
  float sc = gamma[c] * rs;
  g_scale[c] = sc;
  g_shift[c] = fmaf(-mean, sc, beta[c]);
}

__global__ void bn_apply_kernel(float* __restrict__ out) {
  int t = blockIdx.x * blockDim.x + threadIdx.x;
  if (t >= NH / 4) return;
  float4 a = ((float4*)out)[t];
  int c = (t * 4) & (D_H - 1);
  a.x = fmaf(elu_f(a.x), g_scale[c + 0], g_shift[c + 0]);
  a.y = fmaf(elu_f(a.y), g_scale[c + 1], g_shift[c + 1]);
  a.z = fmaf(elu_f(a.z), g_scale[c + 2], g_shift[c + 2]);
  a.w = fmaf(elu_f(a.w), g_scale[c + 3], g_shift[c + 3]);
  ((float4*)out)[t] = a;
}

extern "C" void kernel_launch(void* const* d_in, const int* in_sizes, int n_in,
                              void* d_out, int out_size) {
  const float* data  = (const float*)d_in[0];
  const int*   aidx  = (const int*)d_in[1];     // int32 [2, E]
  const float* avals = (const float*)d_in[2];
  const float* W     = (const float*)d_in[3];
  const float* gamma = (const float*)d_in[4];
  const float* beta  = (const float*)d_in[5];
  float* out = (float*)d_out;

  unsigned keys[4][2];
  for (unsigned j = 0; j < 4; j++) {
    unsigned x0 = 0u, x1 = j;
    tf2x32(0u, 42u, x0, x1);
    keys[j][0] = x0; keys[j][1] = x1;
  }

  cudaMemsetAsync(out, 0, (size_t)NH * sizeof(float), 0);
  zero_stats_kernel<<<1, D_H>>>();
  wprep_kernel<<<(64 * 16 * 32 + 255) / 256, 256>>>(W);
  gemm_rng_kernel<<<(N_NODES + 127) / 128, 256>>>(data,
      keys[0][0], keys[0][1], keys[1][0], keys[1][1], keys[2][0], keys[2][1]);
  {
    int warps = (N_EDGES + EPW - 1) / EPW;
    spmm_kernel<<<(warps * 32 + 255) / 256, 256>>>(aidx, avals, out,
                                                   keys[3][0], keys[3][1]);
  }
  stats_kernel<<<592, 256>>>(out);
  finalize_params_kernel<<<1, D_H>>>(gamma, beta);
  bn_apply_kernel<<<(NH / 4 + 255) / 256, 256>>>(out);
}